// round 11
// baseline (speedup 1.0000x reference)
#include <cuda_runtime.h>
#include <cuda_fp16.h>
#include <cstdint>

// Problem sizes (fixed by the dataset). All tensors are float32 on the wire.
static constexpr int M = 128;
static constexpr int K = 4096;
static constexpr int N = 11008;

static constexpr int BN = 128;     // 86 CTAs exactly, single wave
static constexpr int BK = 64;
static constexpr int STAGES = 6;
static constexpr int ITERS = K / BK;   // 64

static constexpr int B_BYTES = BK * BN * 2;           // 16384 (f16 in smem)
static constexpr int SMEM_TOTAL = STAGES * B_BYTES;   // 98304 (B tiles only)

// A as pre-permuted mma fragments: [mb(8)][k16(256)][lane(32)] x 16B.
// Each uint4 = {a0,a1,a2,a3} of mma.m16n8k16 for that (m16, k16) tile.
__device__ uint4 g_xa[8 * 256 * 32];   // 1 MB, L2-resident

// ---------------------------------------------------------------------------
// Kernel 1: per-(16x64) block mean|x| threshold; emit masked A as permuted
// fragment vectors (one LDG.128 per consumer fragment later).
// ---------------------------------------------------------------------------
__global__ void mask_kernel(const float* __restrict__ x) {
    __shared__ float warp_part[4];
    __shared__ int flag;
    __shared__ __half s[16 * 64];   // masked f16 tile
    const int kb = blockIdx.x;      // 0..63  (k64 block)
    const int mb = blockIdx.y;      // 0..7   (m16 block)
    const int tid = threadIdx.x;    // 128 threads
    const int r  = tid >> 3;        // 0..15 row within block
    const int cg = tid & 7;         // 0..7 col-group (8 floats each)
    const float* p = x + (size_t)(mb * 16 + r) * K + kb * 64 + cg * 8;

    float4 v0 = *reinterpret_cast<const float4*>(p);
    float4 v1 = *reinterpret_cast<const float4*>(p + 4);
    float ssum = fabsf(v0.x) + fabsf(v0.y) + fabsf(v0.z) + fabsf(v0.w)
               + fabsf(v1.x) + fabsf(v1.y) + fabsf(v1.z) + fabsf(v1.w);
#pragma unroll
    for (int o = 16; o; o >>= 1) ssum += __shfl_xor_sync(0xffffffffu, ssum, o);
    if ((tid & 31) == 0) warp_part[tid >> 5] = ssum;
    __syncthreads();
    if (tid == 0) {
        float t = warp_part[0] + warp_part[1] + warp_part[2] + warp_part[3];
        flag = (t * (1.0f / 1024.0f)) > 0.8f ? 1 : 0;
    }
    __syncthreads();

    // masked f16 into smem tile s[16][64]
    {
        __half2* dst = reinterpret_cast<__half2*>(s + r * 64 + cg * 8);
        if (flag) {
            dst[0] = __floats2half2_rn(v0.x, v0.y);
            dst[1] = __floats2half2_rn(v0.z, v0.w);
            dst[2] = __floats2half2_rn(v1.x, v1.y);
            dst[3] = __floats2half2_rn(v1.z, v1.w);
        } else {
            dst[0] = __floats2half2_rn(0.f, 0.f);
            dst[1] = __floats2half2_rn(0.f, 0.f);
            dst[2] = __floats2half2_rn(0.f, 0.f);
            dst[3] = __floats2half2_rn(0.f, 0.f);
        }
    }
    __syncthreads();

    // permute: thread -> one fragment vector of one k16 sub-block
    const int q    = tid >> 5;       // 0..3: k16 within k64
    const int lane = tid & 31;
    const int fr   = lane >> 2;      // fragment row group 0..7
    const int fc   = (lane & 3) * 2; // fragment col base within k16
    const int c0   = q * 16 + fc;
    const __half2* sh = reinterpret_cast<const __half2*>(s);
    // rows of s are 64 halves = 32 half2; col pairs are half2-aligned (fc even)
    uint4 u;
    u.x = *reinterpret_cast<const uint32_t*>(&sh[(fr)     * 32 + (c0 >> 1)]);
    u.y = *reinterpret_cast<const uint32_t*>(&sh[(fr + 8) * 32 + (c0 >> 1)]);
    u.z = *reinterpret_cast<const uint32_t*>(&sh[(fr)     * 32 + ((c0 + 8) >> 1)]);
    u.w = *reinterpret_cast<const uint32_t*>(&sh[(fr + 8) * 32 + ((c0 + 8) >> 1)]);
    g_xa[((mb * 256 + kb * 4 + q) * 32) + lane] = u;
}

// ---------------------------------------------------------------------------
// PTX helpers (non-'a' features only)
// ---------------------------------------------------------------------------
__device__ __forceinline__ uint32_t smem_u32(const void* p) {
    uint32_t a;
    asm("{ .reg .u64 t; cvta.to.shared.u64 t, %1; cvt.u32.u64 %0, t; }" : "=r"(a) : "l"(p));
    return a;
}
__device__ __forceinline__ void ldsm_x4_t(uint32_t (&r)[4], uint32_t addr) {
    asm volatile("ldmatrix.sync.aligned.m8n8.x4.trans.shared.b16 {%0,%1,%2,%3}, [%4];"
                 : "=r"(r[0]), "=r"(r[1]), "=r"(r[2]), "=r"(r[3]) : "r"(addr));
}
__device__ __forceinline__ void mma16816(float (&d)[4], uint32_t a0, uint32_t a1,
                                         uint32_t a2, uint32_t a3,
                                         uint32_t b0, uint32_t b1) {
    asm volatile(
        "mma.sync.aligned.m16n8k16.row.col.f32.f16.f16.f32 "
        "{%0,%1,%2,%3}, {%4,%5,%6,%7}, {%8,%9}, {%0,%1,%2,%3};"
        : "+f"(d[0]), "+f"(d[1]), "+f"(d[2]), "+f"(d[3])
        : "r"(a0), "r"(a1), "r"(a2), "r"(a3), "r"(b0), "r"(b1));
}
__device__ __forceinline__ uint32_t pack_h2(float lo, float hi) {
    __half2 h = __floats2half2_rn(lo, hi);
    return *reinterpret_cast<uint32_t*>(&h);
}

// ---------------------------------------------------------------------------
// Kernel 2: GEMM  out[128, 11008] = xm @ W + bias
//   256 threads. Warps 0-3: consumers (2x2 grid of 64x64 tiles); A fragments
//   come straight from g_xa via L2-resident LDG.128 (one-ks-ahead prefetch),
//   B via ldmatrix from smem. Warps 4-7: B producers (LDG f32 -> F2FP -> STS
//   f16), 6-stage ring, distance-2 slot, one __syncthreads per iteration.
//   A never touches shared memory -> no cp.async, no A-ldmatrix.
// ---------------------------------------------------------------------------
__global__ void __launch_bounds__(256, 1)
gemm_kernel(const float* __restrict__ w,
            const float* __restrict__ bias,
            float* __restrict__ out) {
    extern __shared__ char smem[];
    const uint32_t sb = smem_u32(smem);
    const int tid = threadIdx.x;
    const int wid = tid >> 5;
    const int lane = tid & 31;
    const int n_cta = blockIdx.x * BN;

    if (wid >= 4) {
        // ---------------- B producers (128 threads) ----------------
        const int ptid = tid - 128;          // 0..127
        // B tile: [64 k-rows][128 halves] = 256B rows, 16x16B chunks,
        // chunk ^= 2*(krow&7)  (R4 swizzle, proven)
        const int b_row = ptid >> 4;         // 0..7, +8*i
        const int b_chk = ptid & 15;
        const float* gB = w + (size_t)b_row * N + n_cta + b_chk * 8;
        const uint32_t sB_st = sb + b_row * 256 + ((b_chk ^ ((b_row & 7) << 1)) << 4);

        float4 bbuf[16];
        auto ldg_B = [&](int kblk) {
#pragma unroll
            for (int i = 0; i < 8; i++) {
                const float* src = gB + (size_t)(kblk * BK + i * 8) * N;
                bbuf[2 * i]     = *reinterpret_cast<const float4*>(src);
                bbuf[2 * i + 1] = *reinterpret_cast<const float4*>(src + 4);
            }
        };
        auto sts_B = [&](int stage) {
#pragma unroll
            for (int i = 0; i < 8; i++) {
                uint4 u;
                u.x = pack_h2(bbuf[2 * i].x,     bbuf[2 * i].y);
                u.y = pack_h2(bbuf[2 * i].z,     bbuf[2 * i].w);
                u.z = pack_h2(bbuf[2 * i + 1].x, bbuf[2 * i + 1].y);
                u.w = pack_h2(bbuf[2 * i + 1].z, bbuf[2 * i + 1].w);
                *reinterpret_cast<uint4*>(
                    smem + (sB_st - sb) + stage * B_BYTES + i * (8 * 256)) = u;
            }
        };

        // prologue: stages 0,1 stored; block 2 staged in regs
        ldg_B(0); sts_B(0);
        ldg_B(1); sts_B(1);
        ldg_B(2);
        __syncthreads();                      // (P) stages 0,1 published

        int s_w = 2;                          // stage slot of block j+2
        for (int j = 0; j < ITERS; ++j) {
            __syncthreads();                  // top-of-iter: stage j readable
            if (j < ITERS - 2) sts_B(s_w);    // write block j+2
            if (j < ITERS - 3) ldg_B(j + 3);  // fetch block j+3
            if (++s_w == STAGES) s_w = 0;
        }
        return;
    }

    // ---------------- consumers (4 warps, 2x2 grid of 64x64 tiles) ----------
    const int wr = wid >> 1;                  // 0/1 -> m offset
    const int wc = wid & 1;                   // 0/1 -> n offset
    const int n_w = wc * 64;

    float acc[4][4][4];                       // first n8 of each n16 group
    float acc2[4][4][4];                      // second n8
#pragma unroll
    for (int a = 0; a < 4; a++)
#pragma unroll
        for (int b = 0; b < 4; b++)
#pragma unroll
            for (int c = 0; c < 4; c++) { acc[a][b][c] = 0.f; acc2[a][b][c] = 0.f; }

    // A fragment source: g_xa[((wr*4+im)*256 + it*4+ks)*32 + lane]
    const uint4* ga = g_xa + lane;
    const size_t mb_base = (size_t)(wr * 4) * 256 * 32;

    const int b_k_lo = ((lane >> 3) & 1) * 8 + (lane & 7);  // ldmatrix B k row
    const int b_c_hi = lane >> 4;             // n-chunk select

    // prefetch A frags for (it=0, ks=0)
    uint32_t apre[2][4][4];
#pragma unroll
    for (int im = 0; im < 4; ++im) {
        uint4 v = __ldg(ga + mb_base + (size_t)im * 256 * 32);
        apre[0][im][0] = v.x; apre[0][im][1] = v.y;
        apre[0][im][2] = v.z; apre[0][im][3] = v.w;
    }
    __syncthreads();                          // (P)

    int s_cur = 0;
    for (int it = 0; it < ITERS; ++it) {
        __syncthreads();                      // stage `it` published
        const uint32_t stB = sb + s_cur * B_BYTES;
        if (++s_cur == STAGES) s_cur = 0;

#pragma unroll
        for (int ks = 0; ks < 4; ++ks) {
            const int cb = ks & 1;            // current A buffer
            // prefetch next k16's A frags (next it's ks0 when ks==3)
            if (!(it == ITERS - 1 && ks == 3)) {
                const int nit = (ks == 3) ? it + 1 : it;
                const int nks = (ks + 1) & 3;
                const size_t koff = (size_t)(nit * 4 + nks) * 32;
#pragma unroll
                for (int im = 0; im < 4; ++im) {
                    uint4 v = __ldg(ga + mb_base + ((size_t)im * 256 * 32) + koff);
                    apre[cb ^ 1][im][0] = v.x; apre[cb ^ 1][im][1] = v.y;
                    apre[cb ^ 1][im][2] = v.z; apre[cb ^ 1][im][3] = v.w;
                }
            }
#pragma unroll
            for (int in2 = 0; in2 < 4; ++in2) {
                uint32_t bfr[4];
                const int krow = ks * 16 + b_k_lo;
                const int chk = ((n_w >> 3) + 2 * in2 + b_c_hi) ^ ((krow & 7) << 1);
                ldsm_x4_t(bfr, stB + krow * 256 + (chk << 4));
#pragma unroll
                for (int im = 0; im < 4; ++im) {
                    mma16816(acc[im][in2], apre[cb][im][0], apre[cb][im][1],
                             apre[cb][im][2], apre[cb][im][3], bfr[0], bfr[1]);
                    mma16816(acc2[im][in2], apre[cb][im][0], apre[cb][im][1],
                             apre[cb][im][2], apre[cb][im][3], bfr[2], bfr[3]);
                }
            }
        }
    }

    // ---------------- epilogue: +bias, f32 store ----------------
    const int g = lane >> 2;
    const int t = lane & 3;
#pragma unroll
    for (int im = 0; im < 4; ++im) {
        const int m0 = wr * 64 + im * 16 + g;
#pragma unroll
        for (int in2 = 0; in2 < 4; ++in2) {
            const int n0 = n_cta + n_w + in2 * 16 + 2 * t;
            const float2 bz0 = *reinterpret_cast<const float2*>(bias + n0);
            const float2 bz1 = *reinterpret_cast<const float2*>(bias + n0 + 8);
            float2* p0 = reinterpret_cast<float2*>(out + (size_t)m0 * N + n0);
            float2* p1 = reinterpret_cast<float2*>(out + (size_t)(m0 + 8) * N + n0);
            p0[0] = make_float2(acc[im][in2][0] + bz0.x, acc[im][in2][1] + bz0.y);
            p1[0] = make_float2(acc[im][in2][2] + bz0.x, acc[im][in2][3] + bz0.y);
            p0[4] = make_float2(acc2[im][in2][0] + bz1.x, acc2[im][in2][1] + bz1.y);
            p1[4] = make_float2(acc2[im][in2][2] + bz1.x, acc2[im][in2][3] + bz1.y);
        }
    }
}

// ---------------------------------------------------------------------------
// Host launch
// ---------------------------------------------------------------------------
extern "C" void kernel_launch(void* const* d_in, const int* in_sizes, int n_in,
                              void* d_out, int out_size) {
    (void)in_sizes; (void)n_in; (void)out_size;
    const float* x    = (const float*)d_in[0];
    const float* w    = (const float*)d_in[1];
    const float* bias = (const float*)d_in[2];
    float* out        = (float*)d_out;

    mask_kernel<<<dim3(K / 64, M / 16), 128>>>(x);

    cudaFuncSetAttribute(gemm_kernel, cudaFuncAttributeMaxDynamicSharedMemorySize,
                         SMEM_TOTAL);
    gemm_kernel<<<N / BN, 256, SMEM_TOTAL>>>(w, bias, out);
}

// round 12
// speedup vs baseline: 1.3735x; 1.3735x over previous
#include <cuda_runtime.h>
#include <cuda_fp16.h>
#include <cstdint>

// Problem sizes (fixed by the dataset). All tensors are float32 on the wire.
static constexpr int M = 128;
static constexpr int K = 4096;
static constexpr int N = 11008;

static constexpr int BN = 128;     // per CTA (two independent n-64 halves)
static constexpr int BNH = 64;     // per pipeline group
static constexpr int BK = 64;
static constexpr int STAGES = 4;
static constexpr int ITERS = K / BK;   // 64

static constexpr int A_BYTES = 128 * BK * 2;          // 16384 f16
static constexpr int B_BYTES = BK * BNH * 2;          // 8192  f16
static constexpr int STAGE_BYTES = A_BYTES + B_BYTES; // 24576
static constexpr int HALF_BYTES = STAGES * STAGE_BYTES; // 98304
static constexpr int SMEM_TOTAL = 2 * HALF_BYTES;       // 196608

// masked-x scratch in fp16 (device global: no allocations allowed)
__device__ __half g_xm[M * K];

// ---------------------------------------------------------------------------
// Kernel 1: per-(16x64) block mean|x| threshold; write masked x as fp16
// ---------------------------------------------------------------------------
__global__ void mask_kernel(const float* __restrict__ x) {
    __shared__ float warp_part[4];
    __shared__ int flag;
    const int kb = blockIdx.x;      // 0..63
    const int mb = blockIdx.y;      // 0..7
    const int tid = threadIdx.x;    // 128 threads
    const int r  = tid >> 3;        // 0..15 row within block
    const int cg = tid & 7;         // 0..7 col-group (8 floats each)
    const float* p = x + (size_t)(mb * 16 + r) * K + kb * 64 + cg * 8;

    float4 v0 = *reinterpret_cast<const float4*>(p);
    float4 v1 = *reinterpret_cast<const float4*>(p + 4);
    float s = fabsf(v0.x) + fabsf(v0.y) + fabsf(v0.z) + fabsf(v0.w)
            + fabsf(v1.x) + fabsf(v1.y) + fabsf(v1.z) + fabsf(v1.w);
#pragma unroll
    for (int o = 16; o; o >>= 1) s += __shfl_xor_sync(0xffffffffu, s, o);
    if ((tid & 31) == 0) warp_part[tid >> 5] = s;
    __syncthreads();
    if (tid == 0) {
        float t = warp_part[0] + warp_part[1] + warp_part[2] + warp_part[3];
        flag = (t * (1.0f / 1024.0f)) > 0.8f ? 1 : 0;
    }
    __syncthreads();

    uint4 outv;
    if (flag) {
        __half2 h0 = __floats2half2_rn(v0.x, v0.y);
        __half2 h1 = __floats2half2_rn(v0.z, v0.w);
        __half2 h2 = __floats2half2_rn(v1.x, v1.y);
        __half2 h3 = __floats2half2_rn(v1.z, v1.w);
        outv.x = *reinterpret_cast<uint32_t*>(&h0);
        outv.y = *reinterpret_cast<uint32_t*>(&h1);
        outv.z = *reinterpret_cast<uint32_t*>(&h2);
        outv.w = *reinterpret_cast<uint32_t*>(&h3);
    } else {
        outv = make_uint4(0u, 0u, 0u, 0u);
    }
    *reinterpret_cast<uint4*>(g_xm + (size_t)(mb * 16 + r) * K + kb * 64 + cg * 8) = outv;
}

// ---------------------------------------------------------------------------
// PTX helpers (non-'a' features only)
// ---------------------------------------------------------------------------
__device__ __forceinline__ uint32_t smem_u32(const void* p) {
    uint32_t a;
    asm("{ .reg .u64 t; cvta.to.shared.u64 t, %1; cvt.u32.u64 %0, t; }" : "=r"(a) : "l"(p));
    return a;
}
__device__ __forceinline__ void cp_async16(uint32_t dst, const void* src) {
    asm volatile("cp.async.cg.shared.global [%0], [%1], 16;" :: "r"(dst), "l"(src) : "memory");
}
__device__ __forceinline__ void cp_commit() {
    asm volatile("cp.async.commit_group;" ::: "memory");
}
template <int NN>
__device__ __forceinline__ void cp_wait() {
    asm volatile("cp.async.wait_group %0;" :: "n"(NN) : "memory");
}
__device__ __forceinline__ void bar_sync(int id) {
    asm volatile("bar.sync %0, 256;" :: "r"(id) : "memory");
}
__device__ __forceinline__ void ldsm_x4(uint32_t (&r)[4], uint32_t addr) {
    asm volatile("ldmatrix.sync.aligned.m8n8.x4.shared.b16 {%0,%1,%2,%3}, [%4];"
                 : "=r"(r[0]), "=r"(r[1]), "=r"(r[2]), "=r"(r[3]) : "r"(addr));
}
__device__ __forceinline__ void ldsm_x4_t(uint32_t (&r)[4], uint32_t addr) {
    asm volatile("ldmatrix.sync.aligned.m8n8.x4.trans.shared.b16 {%0,%1,%2,%3}, [%4];"
                 : "=r"(r[0]), "=r"(r[1]), "=r"(r[2]), "=r"(r[3]) : "r"(addr));
}
__device__ __forceinline__ void mma16816(float (&d)[4], const uint32_t (&a)[4],
                                         uint32_t b0, uint32_t b1) {
    asm volatile(
        "mma.sync.aligned.m16n8k16.row.col.f32.f16.f16.f32 "
        "{%0,%1,%2,%3}, {%4,%5,%6,%7}, {%8,%9}, {%0,%1,%2,%3};"
        : "+f"(d[0]), "+f"(d[1]), "+f"(d[2]), "+f"(d[3])
        : "r"(a[0]), "r"(a[1]), "r"(a[2]), "r"(a[3]), "r"(b0), "r"(b1));
}
__device__ __forceinline__ uint32_t pack_h2(float lo, float hi) {
    __half2 h = __floats2half2_rn(lo, hi);
    return *reinterpret_cast<uint32_t*>(&h);
}

// ---------------------------------------------------------------------------
// Kernel 2: TWO independent pipelines per CTA (one per n-64 half).
//   512 threads = 2 groups x (4 consumer warps + 4 producer warps).
//   Each group: own named barrier (1+g), own 4-stage smem ring, own A copy.
//   Per-group logic is exactly the proven R4 kernel with BN=64.
//   Purpose: two independent latency chains per SMSP fill each other's
//   pipeline bubbles (the cross-round-invariant ~1850cyc/iter period).
// ---------------------------------------------------------------------------
__global__ void __launch_bounds__(512, 1)
gemm_kernel(const float* __restrict__ w,
            const float* __restrict__ bias,
            float* __restrict__ out) {
    extern __shared__ char smem[];
    const uint32_t sb = smem_u32(smem);
    const int tid = threadIdx.x;
    const int grp = tid >> 8;                 // 0/1: pipeline group
    const int ltid = tid & 255;               // id within group
    const int lwid = ltid >> 5;               // 0..7 within group
    const int lane = tid & 31;
    const int n_half = blockIdx.x * BN + grp * BNH;
    const uint32_t hb = sb + grp * HALF_BYTES;
    const int barid = 1 + grp;

    if (lwid >= 4) {
        // ---------------- producers (128 threads of this group) -------------
        const int ptid = ltid - 128;         // 0..127
        // A tile: [128 rows][64 halves] = 128B rows, 8 chunks, chunk ^= (row&7)
        const int a_row = ptid >> 3;         // 0..15, +16*i
        const int a_chk = ptid & 7;
        const __half* gA = g_xm + (size_t)a_row * K + a_chk * 8;
        const uint32_t sA_st = hb + a_row * 128 + ((a_chk ^ (a_row & 7)) << 4);
        // B tile: [64 k-rows][64 halves] = 128B rows, 8 chunks, chunk ^= (row&7)
        const int b_row = ptid >> 3;         // 0..15, +16*i
        const int b_chk = ptid & 7;
        const float* gB = w + (size_t)b_row * N + n_half + b_chk * 8;
        const uint32_t sB_st = hb + A_BYTES + b_row * 128 + ((b_chk ^ (b_row & 7)) << 4);

        float4 bbuf[8];                      // one staged f32 B tile (4 rows x 8 f32)

        auto load_A = [&](int stage, int k0) {
#pragma unroll
            for (int i = 0; i < 8; i++)
                cp_async16(sA_st + stage * STAGE_BYTES + i * (16 * 128),
                           gA + k0 + (size_t)i * 16 * K);
        };
        auto ldg_B = [&](int k0) {
#pragma unroll
            for (int i = 0; i < 4; i++) {
                const float* src = gB + (size_t)(k0 + i * 16) * N;
                bbuf[2 * i]     = *reinterpret_cast<const float4*>(src);
                bbuf[2 * i + 1] = *reinterpret_cast<const float4*>(src + 4);
            }
        };
        auto sts_B = [&](int stage) {
#pragma unroll
            for (int i = 0; i < 4; i++) {
                uint4 u;
                u.x = pack_h2(bbuf[2 * i].x,     bbuf[2 * i].y);
                u.y = pack_h2(bbuf[2 * i].z,     bbuf[2 * i].w);
                u.z = pack_h2(bbuf[2 * i + 1].x, bbuf[2 * i + 1].y);
                u.w = pack_h2(bbuf[2 * i + 1].z, bbuf[2 * i + 1].w);
                *reinterpret_cast<uint4*>(
                    smem + (sB_st - sb) + stage * STAGE_BYTES + i * (16 * 128)) = u;
            }
        };

        // prologue: A stages 0..2 in flight; B stages 0,1 stored, block 2 in regs
#pragma unroll
        for (int s = 0; s < STAGES - 1; s++) { load_A(s, s * BK); cp_commit(); }
        ldg_B(0 * BK); sts_B(0);
        ldg_B(1 * BK); sts_B(1);
        ldg_B(2 * BK);

        for (int it = 0; it < ITERS; ++it) {
            cp_wait<STAGES - 2>();           // A of stage `it` arrived
            bar_sync(barid);                 // publish stage `it` to this group
            if (it + 3 < ITERS) load_A((it + 3) & (STAGES - 1), (it + 3) * BK);
            cp_commit();
            if (it + 2 < ITERS) sts_B((it + 2) & (STAGES - 1));
            if (it + 3 < ITERS) ldg_B((it + 3) * BK);
        }
        return;
    }

    // ---------------- consumers (4 warps, 2x2 grid of 64m x 32n tiles) ------
    const int wr = lwid >> 1;                 // 0/1 -> m offset
    const int wc = lwid & 1;                  // 0/1 -> n offset
    const int m_w = wr * 64;
    const int n_w = wc * 32;

    float acc[4][2][4];                       // first n8 of each n16 group
    float acc2[4][2][4];                      // second n8
#pragma unroll
    for (int a = 0; a < 4; a++)
#pragma unroll
        for (int b = 0; b < 2; b++)
#pragma unroll
            for (int c = 0; c < 4; c++) { acc[a][b][c] = 0.f; acc2[a][b][c] = 0.f; }

    const int a_r = m_w + (lane & 15);        // ldmatrix A row
    const int a_c_hi = lane >> 4;             // k-chunk select
    const int b_k_lo = ((lane >> 3) & 1) * 8 + (lane & 7);  // ldmatrix B k row
    const int b_c_hi = lane >> 4;             // n-chunk select

    for (int it = 0; it < ITERS; ++it) {
        bar_sync(barid);                      // stage `it` published
        const uint32_t stA = hb + (it & (STAGES - 1)) * STAGE_BYTES;
        const uint32_t stB = stA + A_BYTES;

#pragma unroll
        for (int ks = 0; ks < 4; ++ks) {
            uint32_t afr[4][4];
#pragma unroll
            for (int im = 0; im < 4; ++im) {
                const int row = a_r + im * 16;
                const int chk = (2 * ks + a_c_hi) ^ (row & 7);
                ldsm_x4(afr[im], stA + row * 128 + (chk << 4));
            }
#pragma unroll
            for (int in2 = 0; in2 < 2; ++in2) {
                uint32_t bfr[4];
                const int krow = ks * 16 + b_k_lo;
                const int chk = (4 * wc + 2 * in2 + b_c_hi) ^ (krow & 7);
                ldsm_x4_t(bfr, stB + krow * 128 + (chk << 4));
#pragma unroll
                for (int im = 0; im < 4; ++im) {
                    mma16816(acc[im][in2], afr[im], bfr[0], bfr[1]);
                    mma16816(acc2[im][in2], afr[im], bfr[2], bfr[3]);
                }
            }
        }
    }

    // ---------------- epilogue: +bias, f32 store ----------------
    const int gr = lane >> 2;
    const int t = lane & 3;
#pragma unroll
    for (int im = 0; im < 4; ++im) {
        const int m0 = m_w + im * 16 + gr;
#pragma unroll
        for (int in2 = 0; in2 < 2; ++in2) {
            const int n0 = n_half + n_w + in2 * 16 + 2 * t;
            const float2 bz0 = *reinterpret_cast<const float2*>(bias + n0);
            const float2 bz1 = *reinterpret_cast<const float2*>(bias + n0 + 8);
            float2* p0 = reinterpret_cast<float2*>(out + (size_t)m0 * N + n0);
            float2* p1 = reinterpret_cast<float2*>(out + (size_t)(m0 + 8) * N + n0);
            p0[0] = make_float2(acc[im][in2][0] + bz0.x, acc[im][in2][1] + bz0.y);
            p1[0] = make_float2(acc[im][in2][2] + bz0.x, acc[im][in2][3] + bz0.y);
            p0[4] = make_float2(acc2[im][in2][0] + bz1.x, acc2[im][in2][1] + bz1.y);
            p1[4] = make_float2(acc2[im][in2][2] + bz1.x, acc2[im][in2][3] + bz1.y);
        }
    }
}

// ---------------------------------------------------------------------------
// Host launch
// ---------------------------------------------------------------------------
extern "C" void kernel_launch(void* const* d_in, const int* in_sizes, int n_in,
                              void* d_out, int out_size) {
    (void)in_sizes; (void)n_in; (void)out_size;
    const float* x    = (const float*)d_in[0];
    const float* w    = (const float*)d_in[1];
    const float* bias = (const float*)d_in[2];
    float* out        = (float*)d_out;

    mask_kernel<<<dim3(K / 64, M / 16), 128>>>(x);

    cudaFuncSetAttribute(gemm_kernel, cudaFuncAttributeMaxDynamicSharedMemorySize,
                         SMEM_TOTAL);
    gemm_kernel<<<N / BN, 512, SMEM_TOTAL>>>(w, bias, out);
}

// round 13
// speedup vs baseline: 1.3741x; 1.0005x over previous
#include <cuda_runtime.h>
#include <cuda_fp16.h>
#include <cstdint>

// Problem sizes (fixed by the dataset). All tensors are float32 on the wire.
static constexpr int M = 128;
static constexpr int K = 4096;
static constexpr int N = 11008;

static constexpr int BN = 128;     // per CTA (two n-64 halves)
static constexpr int BNH = 64;     // per pipeline group
static constexpr int BK = 64;
static constexpr int STAGES = 4;
static constexpr int ITERS = K / BK;   // 64

static constexpr int A_BYTES = 128 * BK * 2;          // 16384 f16 per stage
static constexpr int B_BYTES = BK * BNH * 2;          // 8192  f16 per stage
// smem: shared A ring [0, 64K), B ring g0 [64K, 96K), B ring g1 [96K, 128K)
static constexpr int SMEM_B0 = STAGES * A_BYTES;            // 65536
static constexpr int SMEM_B1 = SMEM_B0 + STAGES * B_BYTES;  // 98304
static constexpr int SMEM_TOTAL = SMEM_B1 + STAGES * B_BYTES; // 131072

// masked-x scratch in fp16 (device global: no allocations allowed)
__device__ __half g_xm[M * K];

// ---------------------------------------------------------------------------
// Kernel 1: per-(16x64) block mean|x| threshold; write masked x as fp16
// ---------------------------------------------------------------------------
__global__ void mask_kernel(const float* __restrict__ x) {
    __shared__ float warp_part[4];
    __shared__ int flag;
    const int kb = blockIdx.x;      // 0..63
    const int mb = blockIdx.y;      // 0..7
    const int tid = threadIdx.x;    // 128 threads
    const int r  = tid >> 3;        // 0..15 row within block
    const int cg = tid & 7;         // 0..7 col-group (8 floats each)
    const float* p = x + (size_t)(mb * 16 + r) * K + kb * 64 + cg * 8;

    float4 v0 = *reinterpret_cast<const float4*>(p);
    float4 v1 = *reinterpret_cast<const float4*>(p + 4);
    float s = fabsf(v0.x) + fabsf(v0.y) + fabsf(v0.z) + fabsf(v0.w)
            + fabsf(v1.x) + fabsf(v1.y) + fabsf(v1.z) + fabsf(v1.w);
#pragma unroll
    for (int o = 16; o; o >>= 1) s += __shfl_xor_sync(0xffffffffu, s, o);
    if ((tid & 31) == 0) warp_part[tid >> 5] = s;
    __syncthreads();
    if (tid == 0) {
        float t = warp_part[0] + warp_part[1] + warp_part[2] + warp_part[3];
        flag = (t * (1.0f / 1024.0f)) > 0.8f ? 1 : 0;
    }
    __syncthreads();

    uint4 outv;
    if (flag) {
        __half2 h0 = __floats2half2_rn(v0.x, v0.y);
        __half2 h1 = __floats2half2_rn(v0.z, v0.w);
        __half2 h2 = __floats2half2_rn(v1.x, v1.y);
        __half2 h3 = __floats2half2_rn(v1.z, v1.w);
        outv.x = *reinterpret_cast<uint32_t*>(&h0);
        outv.y = *reinterpret_cast<uint32_t*>(&h1);
        outv.z = *reinterpret_cast<uint32_t*>(&h2);
        outv.w = *reinterpret_cast<uint32_t*>(&h3);
    } else {
        outv = make_uint4(0u, 0u, 0u, 0u);
    }
    *reinterpret_cast<uint4*>(g_xm + (size_t)(mb * 16 + r) * K + kb * 64 + cg * 8) = outv;
}

// ---------------------------------------------------------------------------
// PTX helpers (non-'a' features only)
// ---------------------------------------------------------------------------
__device__ __forceinline__ uint32_t smem_u32(const void* p) {
    uint32_t a;
    asm("{ .reg .u64 t; cvta.to.shared.u64 t, %1; cvt.u32.u64 %0, t; }" : "=r"(a) : "l"(p));
    return a;
}
__device__ __forceinline__ void cp_async16(uint32_t dst, const void* src) {
    asm volatile("cp.async.cg.shared.global [%0], [%1], 16;" :: "r"(dst), "l"(src) : "memory");
}
__device__ __forceinline__ void cp_commit() {
    asm volatile("cp.async.commit_group;" ::: "memory");
}
template <int NN>
__device__ __forceinline__ void cp_wait() {
    asm volatile("cp.async.wait_group %0;" :: "n"(NN) : "memory");
}
__device__ __forceinline__ void bar_sync(int id, int cnt) {
    asm volatile("bar.sync %0, %1;" :: "r"(id), "r"(cnt) : "memory");
}
__device__ __forceinline__ void ldsm_x4(uint32_t (&r)[4], uint32_t addr) {
    asm volatile("ldmatrix.sync.aligned.m8n8.x4.shared.b16 {%0,%1,%2,%3}, [%4];"
                 : "=r"(r[0]), "=r"(r[1]), "=r"(r[2]), "=r"(r[3]) : "r"(addr));
}
__device__ __forceinline__ void ldsm_x4_t(uint32_t (&r)[4], uint32_t addr) {
    asm volatile("ldmatrix.sync.aligned.m8n8.x4.trans.shared.b16 {%0,%1,%2,%3}, [%4];"
                 : "=r"(r[0]), "=r"(r[1]), "=r"(r[2]), "=r"(r[3]) : "r"(addr));
}
__device__ __forceinline__ void mma16816(float (&d)[4], const uint32_t (&a)[4],
                                         uint32_t b0, uint32_t b1) {
    asm volatile(
        "mma.sync.aligned.m16n8k16.row.col.f32.f16.f16.f32 "
        "{%0,%1,%2,%3}, {%4,%5,%6,%7}, {%8,%9}, {%0,%1,%2,%3};"
        : "+f"(d[0]), "+f"(d[1]), "+f"(d[2]), "+f"(d[3])
        : "r"(a[0]), "r"(a[1]), "r"(a[2]), "r"(a[3]), "r"(b0), "r"(b1));
}
__device__ __forceinline__ uint32_t pack_h2(float lo, float hi) {
    __half2 h = __floats2half2_rn(lo, hi);
    return *reinterpret_cast<uint32_t*>(&h);
}

// ---------------------------------------------------------------------------
// Kernel 2: two B pipelines + ONE shared A ring per CTA.
//   512 threads = 2 groups x (4 consumer + 4 producer warps).
//   Group g consumers: 128m x 64n half (2x2 of 64x32 tiles).
//   A ring (4 stages) loaded by group-0 producers only; published via
//   bar.sync(3, 384) = 256 consumers + g0's 128 producers. B rings are
//   per-group, published via bar.sync(1+g, 256). This halves A cp.async
//   ops + A smem traffic vs R12 (MIO-dispatch model: 1664->1408 cyc/iter).
//   Barrier order per iter (bar3 then barB) is cycle-free.
// ---------------------------------------------------------------------------
__global__ void __launch_bounds__(512, 1)
gemm_kernel(const float* __restrict__ w,
            const float* __restrict__ bias,
            float* __restrict__ out) {
    extern __shared__ char smem[];
    const uint32_t sb = smem_u32(smem);
    const int tid = threadIdx.x;
    const int grp = tid >> 8;                 // 0/1: pipeline group
    const int ltid = tid & 255;               // id within group
    const int lwid = ltid >> 5;               // 0..7 within group
    const int lane = tid & 31;
    const int n_half = blockIdx.x * BN + grp * BNH;
    const uint32_t bbase = sb + (grp ? SMEM_B1 : SMEM_B0);

    if (lwid >= 4) {
        // ---------------- producers (128 threads per group) -----------------
        const int ptid = ltid - 128;         // 0..127
        // B tile: [64 k-rows][64 halves] = 128B rows, 8 chunks, chunk ^= (row&7)
        const int b_row = ptid >> 3;         // 0..15, +16*i
        const int b_chk = ptid & 7;
        const float* gB = w + (size_t)b_row * N + n_half + b_chk * 8;
        const uint32_t sB_st = bbase + b_row * 128 + ((b_chk ^ (b_row & 7)) << 4);

        float4 bbuf[8];                      // staged f32 B (4 rows x 8 f32)
        auto ldg_B = [&](int k0) {
#pragma unroll
            for (int i = 0; i < 4; i++) {
                const float* src = gB + (size_t)(k0 + i * 16) * N;
                bbuf[2 * i]     = *reinterpret_cast<const float4*>(src);
                bbuf[2 * i + 1] = *reinterpret_cast<const float4*>(src + 4);
            }
        };
        auto sts_B = [&](int stage) {
#pragma unroll
            for (int i = 0; i < 4; i++) {
                uint4 u;
                u.x = pack_h2(bbuf[2 * i].x,     bbuf[2 * i].y);
                u.y = pack_h2(bbuf[2 * i].z,     bbuf[2 * i].w);
                u.z = pack_h2(bbuf[2 * i + 1].x, bbuf[2 * i + 1].y);
                u.w = pack_h2(bbuf[2 * i + 1].z, bbuf[2 * i + 1].w);
                *reinterpret_cast<uint4*>(
                    smem + (sB_st - sb) + stage * B_BYTES + i * (16 * 128)) = u;
            }
        };

        if (grp == 0) {
            // A tile: [128 rows][64 halves] = 128B rows, 8 chunks, chunk ^= (row&7)
            const int a_row = ptid >> 3;     // 0..15, +16*i
            const int a_chk = ptid & 7;
            const __half* gA = g_xm + (size_t)a_row * K + a_chk * 8;
            const uint32_t sA_st = sb + a_row * 128 + ((a_chk ^ (a_row & 7)) << 4);
            auto load_A = [&](int stage, int k0) {
#pragma unroll
                for (int i = 0; i < 8; i++)
                    cp_async16(sA_st + stage * A_BYTES + i * (16 * 128),
                               gA + k0 + (size_t)i * 16 * K);
            };

            // prologue: A stages 0..2 in flight; B stages 0,1 stored, blk2 regs
#pragma unroll
            for (int s = 0; s < STAGES - 1; s++) { load_A(s, s * BK); cp_commit(); }
            ldg_B(0 * BK); sts_B(0);
            ldg_B(1 * BK); sts_B(1);
            ldg_B(2 * BK);

            for (int it = 0; it < ITERS; ++it) {
                cp_wait<STAGES - 2>();       // A of stage `it` arrived
                bar_sync(3, 384);            // publish A stage `it`
                bar_sync(1, 256);            // publish B stage `it` (g0)
                if (it + 3 < ITERS) load_A((it + 3) & (STAGES - 1), (it + 3) * BK);
                cp_commit();
                if (it + 2 < ITERS) sts_B((it + 2) & (STAGES - 1));
                if (it + 3 < ITERS) ldg_B((it + 3) * BK);
            }
        } else {
            // group-1 producers: B only
            ldg_B(0 * BK); sts_B(0);
            ldg_B(1 * BK); sts_B(1);
            ldg_B(2 * BK);
            for (int it = 0; it < ITERS; ++it) {
                bar_sync(2, 256);            // publish B stage `it` (g1)
                if (it + 2 < ITERS) sts_B((it + 2) & (STAGES - 1));
                if (it + 3 < ITERS) ldg_B((it + 3) * BK);
            }
        }
        return;
    }

    // ---------------- consumers (4 warps/group, 2x2 of 64m x 32n tiles) -----
    const int wr = lwid >> 1;                 // 0/1 -> m offset
    const int wc = lwid & 1;                  // 0/1 -> n offset
    const int m_w = wr * 64;
    const int n_w = wc * 32;

    float acc[4][2][4];                       // first n8 of each n16 group
    float acc2[4][2][4];                      // second n8
#pragma unroll
    for (int a = 0; a < 4; a++)
#pragma unroll
        for (int b = 0; b < 2; b++)
#pragma unroll
            for (int c = 0; c < 4; c++) { acc[a][b][c] = 0.f; acc2[a][b][c] = 0.f; }

    const int a_r = m_w + (lane & 15);        // ldmatrix A row
    const int a_c_hi = lane >> 4;             // k-chunk select
    const int b_k_lo = ((lane >> 3) & 1) * 8 + (lane & 7);  // ldmatrix B k row
    const int b_c_hi = lane >> 4;             // n-chunk select

    for (int it = 0; it < ITERS; ++it) {
        bar_sync(3, 384);                     // A stage `it` published
        bar_sync(1 + grp, 256);               // B stage `it` published
        const uint32_t stA = sb + (it & (STAGES - 1)) * A_BYTES;
        const uint32_t stB = bbase + (it & (STAGES - 1)) * B_BYTES;

#pragma unroll
        for (int ks = 0; ks < 4; ++ks) {
            uint32_t afr[4][4];
#pragma unroll
            for (int im = 0; im < 4; ++im) {
                const int row = a_r + im * 16;
                const int chk = (2 * ks + a_c_hi) ^ (row & 7);
                ldsm_x4(afr[im], stA + row * 128 + (chk << 4));
            }
#pragma unroll
            for (int in2 = 0; in2 < 2; ++in2) {
                uint32_t bfr[4];
                const int krow = ks * 16 + b_k_lo;
                const int chk = (4 * wc + 2 * in2 + b_c_hi) ^ (krow & 7);
                ldsm_x4_t(bfr, stB + krow * 128 + (chk << 4));
#pragma unroll
                for (int im = 0; im < 4; ++im) {
                    mma16816(acc[im][in2], afr[im], bfr[0], bfr[1]);
                    mma16816(acc2[im][in2], afr[im], bfr[2], bfr[3]);
                }
            }
        }
    }

    // ---------------- epilogue: +bias, f32 store ----------------
    const int gr = lane >> 2;
    const int t = lane & 3;
#pragma unroll
    for (int im = 0; im < 4; ++im) {
        const int m0 = m_w + im * 16 + gr;
#pragma unroll
        for (int in2 = 0; in2 < 2; ++in2) {
            const int n0 = n_half + n_w + in2 * 16 + 2 * t;
            const float2 bz0 = *reinterpret_cast<const float2*>(bias + n0);
            const float2 bz1 = *reinterpret_cast<const float2*>(bias + n0 + 8);
            float2* p0 = reinterpret_cast<float2*>(out + (size_t)m0 * N + n0);
            float2* p1 = reinterpret_cast<float2*>(out + (size_t)(m0 + 8) * N + n0);
            p0[0] = make_float2(acc[im][in2][0] + bz0.x, acc[im][in2][1] + bz0.y);
            p1[0] = make_float2(acc[im][in2][2] + bz0.x, acc[im][in2][3] + bz0.y);
            p0[4] = make_float2(acc2[im][in2][0] + bz1.x, acc2[im][in2][1] + bz1.y);
            p1[4] = make_float2(acc2[im][in2][2] + bz1.x, acc2[im][in2][3] + bz1.y);
        }
    }
}

// ---------------------------------------------------------------------------
// Host launch
// ---------------------------------------------------------------------------
extern "C" void kernel_launch(void* const* d_in, const int* in_sizes, int n_in,
                              void* d_out, int out_size) {
    (void)in_sizes; (void)n_in; (void)out_size;
    const float* x    = (const float*)d_in[0];
    const float* w    = (const float*)d_in[1];
    const float* bias = (const float*)d_in[2];
    float* out        = (float*)d_out;

    mask_kernel<<<dim3(K / 64, M / 16), 128>>>(x);

    cudaFuncSetAttribute(gemm_kernel, cudaFuncAttributeMaxDynamicSharedMemorySize,
                         SMEM_TOTAL);
    gemm_kernel<<<N / BN, 512, SMEM_TOTAL>>>(w, bias, out);
}